// round 15
// baseline (speedup 1.0000x reference)
#include <cuda_runtime.h>
#include <cuda_fp16.h>

// Fused curve-LUT apply (trilinear grid_sample over 8x256x256 control grid + tanh).
//
// R15 = R12 pixel loop (stride-4 bank-tiled fp16 z-pair layout, 2 rows/thread,
// sequential k-loop, 32-reg profile) with a 32x64 TILE / 1024 THREADS:
// staging (measured ~11us total = latency ramp + barrier per CTA) now
// amortizes over 2048 px/CTA instead of 1024. 2 CTAs x 1024 thr = 2048
// thr/SM = same full occupancy as R12's 4x512. Patch 10x18 points,
// smem 25.9KB (x2 CTAs = 51.8KB). Banking: bank = 4*dx + zi, 8 points tile
// 32 banks exactly -> conflict-free LDS (established R12).
// z-range trick (R10): iz = 3.5x+3.5 in [3.5,7) -> zi in {0..3}.

#define TW 32
#define TH 64
#define XS 10
#define YS 18
#define NP (XS * YS)       // 180 points
#define ASTR (NP * 4)      // 720 half2 per (i,c) array
#define NCOLS (9 * NP)     // 1620 staging columns
#define NTHREADS 1024

__device__ __forceinline__ float fast_tanh(float v) {
    float y;
    asm("tanh.approx.f32 %0, %1;" : "=f"(y) : "f"(v));
    return y;
}

__global__ __launch_bounds__(NTHREADS, 2)
void curve_apply_kernel(const float* __restrict__ x,
                        const float* __restrict__ param,
                        float* __restrict__ out)
{
    __shared__ __align__(16) __half2 sh[9 * ASTR];   // 6480 half2 = 25,920 B

    const int b  = blockIdx.z;
    const int w0 = blockIdx.x * TW;
    const int h0 = blockIdx.y * TH;
    const float r = 255.0f / 1023.0f;
    const int xbase = (int)floorf((float)w0 * r);
    const int ybase = (int)floorf((float)h0 * r);
    const int tid = threadIdx.x;

    // ---- Column-wise staging: z-planes 3..7, one STS.128 per column ----
    const float* prm = param + (size_t)b * 72 * 65536;
    #pragma unroll 1
    for (int col = tid; col < NCOLS; col += NTHREADS) {
        int arr = col / NP;            // 0..8 -> (i, c)
        int pt  = col - arr * NP;      // 0..179 (consecutive per lane)
        int c   = arr % 3;
        int i   = arr / 3;
        int dy  = pt / XS;
        int dx  = pt - dy * XS;
        int yy  = min(ybase + dy, 255);
        int xx  = min(xbase + dx, 255);
        const float* src = prm + (size_t)(c * 24 + i * 8 + 3) * 65536 + yy * 256 + xx;
        float v[5];
        #pragma unroll
        for (int z = 0; z < 5; z++) v[z] = __ldg(src + z * 65536);
        __half2 pr[4];
        #pragma unroll
        for (int j = 0; j < 4; j++) pr[j] = __floats2half2_rn(v[j], v[j + 1]);
        *(uint4*)(sh + arr * ASTR + pt * 4) = *(uint4*)pr;
    }
    __syncthreads();

    // ---- Pixel loop: 32 warps, lane = x, rows h and h+32 per thread ----
    const int lane = tid & 31;
    const int rowi = tid >> 5;          // 0..31
    const int w = w0 + lane;

    float ixf = fminf((float)w * r, 255.0f);
    float x0f = floorf(ixf);
    float wx  = ixf - x0f;
    int   x0  = (int)x0f;
    int   dx0 = x0 - xbase;
    int   dx1 = min(x0 + 1, 255) - xbase;

    const float* xb = x   + (size_t)b * 3 * 1048576;
    float*       ob = out + (size_t)b * 3 * 1048576;

    const int h_a = h0 + rowi;
    const int h_b = h_a + 32;
    const int pixA = h_a * 1024 + w;
    const int pixB = h_b * 1024 + w;

    float gz_[2][3];
    gz_[0][0] = __ldg(xb + pixA);
    gz_[0][1] = __ldg(xb + 1048576 + pixA);
    gz_[0][2] = __ldg(xb + 2097152 + pixA);
    gz_[1][0] = __ldg(xb + pixB);
    gz_[1][1] = __ldg(xb + 1048576 + pixB);
    gz_[1][2] = __ldg(xb + 2097152 + pixB);

    #pragma unroll
    for (int k = 0; k < 2; k++) {
        const int h   = (k == 0) ? h_a : h_b;
        const int pix = (k == 0) ? pixA : pixB;

        float iyf = fminf((float)h * r, 255.0f);
        float y0f = floorf(iyf);
        float wy  = iyf - y0f;
        int   y0  = (int)y0f;
        int   dy0 = y0 - ybase;
        int   dy1 = min(y0 + 1, 255) - ybase;

        int cb00 = (dy0 * XS + dx0) * 4;
        int cb01 = (dy0 * XS + dx1) * 4;
        int cb10 = (dy1 * XS + dx0) * 4;
        int cb11 = (dy1 * XS + dx1) * 4;

        float w11 = wy * wx;
        float w10 = wy - w11;
        float w01 = wx - w11;
        float w00 = 1.0f - wy - wx + w11;

        const __half2 hw00 = __half2half2(__float2half_rn(w00));
        const __half2 hw01 = __half2half2(__float2half_rn(w01));
        const __half2 hw10 = __half2half2(__float2half_rn(w10));
        const __half2 hw11 = __half2half2(__float2half_rn(w11));

        float acc0 = 0.f, acc1 = 0.f, acc2 = 0.f;

        #pragma unroll
        for (int i = 0; i < 3; i++) {
            float gz  = gz_[k][i];
            float izf = fminf(fmaxf(fmaf(gz, 3.5f, 3.5f), 3.5f), 6.99951171875f);
            float z0f = floorf(izf);
            float wz  = izf - z0f;
            int   zi  = (int)z0f - 3;            // 0..3
            const __half2* base = sh + (i * 3) * ASTR + zi;

            #define CHAN(COFF, ACC)                                           \
            {                                                                 \
                const __half2* p = base + (COFF) * ASTR;                      \
                __half2 t = __hfma2(hw01, p[cb01], __hmul2(hw00, p[cb00]));   \
                __half2 u = __hfma2(hw11, p[cb11], __hmul2(hw10, p[cb10]));   \
                t = __hadd2(t, u);                                            \
                float2 f = __half22float2(t);                                 \
                ACC += fmaf(wz, f.y - f.x, f.x);                              \
            }
            CHAN(0, acc0)
            CHAN(1, acc1)
            CHAN(2, acc2)
            #undef CHAN
        }

        ob[pix]           = fast_tanh(acc0);
        ob[1048576 + pix] = fast_tanh(acc1);
        ob[2097152 + pix] = fast_tanh(acc2);
    }
}

extern "C" void kernel_launch(void* const* d_in, const int* in_sizes, int n_in,
                              void* d_out, int out_size)
{
    const float* x     = (const float*)d_in[0];   // [4,3,1024,1024] fp32
    const float* param = (const float*)d_in[1];   // [4,72,256,256]  fp32
    float*       out   = (float*)d_out;           // [4,3,1024,1024] fp32

    dim3 grid(1024 / TW, 1024 / TH, 4);
    curve_apply_kernel<<<grid, NTHREADS>>>(x, param, out);
}

// round 16
// speedup vs baseline: 1.1124x; 1.1124x over previous
#include <cuda_runtime.h>
#include <cuda_fp16.h>

// Fused curve-LUT apply (trilinear grid_sample over 8x256x256 control grid + tanh).
//
// R16 = R12 champion (perfect stride-4 bank tiling: bank = 4*dx + zi so 8
// consecutive control points tile all 32 banks; z-range-restricted fp16
// overlapping pairs, zi in {0..3} since iz = 3.5x+3.5 in [3.5,7);
// one-STS.128 column staging; 32x32 tile, 512 thr, 14.4KB smem, 4 CTAs/SM)
// with ONE reorder: the 6 gz LDGs are issued AFTER the staging loop but
// BEFORE __syncthreads(), so their latency overlaps the barrier wait
// (R14 showed loads before staging extend live ranges and regress; R12
// loaded them after the barrier, exposing the full latency).

#define TW 32
#define TH 32
#define XS 10
#define YS 10
#define NP (XS * YS)       // 100 points
#define ASTR 400           // half2 per (i,c) array: 100 pts * 4 zi-pairs
#define NTHREADS 512

__device__ __forceinline__ float fast_tanh(float v) {
    float y;
    asm("tanh.approx.f32 %0, %1;" : "=f"(y) : "f"(v));
    return y;
}

__global__ __launch_bounds__(NTHREADS, 4)
void curve_apply_kernel(const float* __restrict__ x,
                        const float* __restrict__ param,
                        float* __restrict__ out)
{
    __shared__ __align__(16) __half2 sh[9 * ASTR];   // 3600 half2 = 14,400 B

    const int b  = blockIdx.z;
    const int w0 = blockIdx.x * TW;
    const int h0 = blockIdx.y * TH;
    const float r = 255.0f / 1023.0f;
    const int xbase = (int)floorf((float)w0 * r);
    const int ybase = (int)floorf((float)h0 * r);
    const int tid = threadIdx.x;

    // ---- Column-wise staging: z-planes 3..7, one STS.128 per column ----
    const float* prm = param + (size_t)b * 72 * 65536;
    for (int col = tid; col < 900; col += NTHREADS) {
        int rest = col / 100;          // 0..8 -> (i, c)
        int pt   = col - rest * 100;   // 0..99 (consecutive per lane)
        int c    = rest % 3;
        int i    = rest / 3;
        int dy   = pt / 10;
        int dx   = pt - dy * 10;
        int yy   = min(ybase + dy, 255);
        int xx   = min(xbase + dx, 255);
        const float* src = prm + (size_t)(c * 24 + i * 8 + 3) * 65536 + yy * 256 + xx;
        float v[5];
        #pragma unroll
        for (int z = 0; z < 5; z++) v[z] = __ldg(src + z * 65536);
        __half2 pr[4];
        #pragma unroll
        for (int j = 0; j < 4; j++) pr[j] = __floats2half2_rn(v[j], v[j + 1]);
        *(uint4*)(sh + (i * 3 + c) * ASTR + pt * 4) = *(uint4*)pr;
    }

    // ---- gz prefetch: issued before the barrier, consumed after it ----
    const int lane = tid & 31;
    const int rowi = tid >> 5;
    const int w = w0 + lane;
    const int h_a = h0 + rowi;
    const int h_b = h_a + 16;
    const int pixA = h_a * 1024 + w;
    const int pixB = h_b * 1024 + w;

    const float* xb = x   + (size_t)b * 3 * 1048576;
    float*       ob = out + (size_t)b * 3 * 1048576;

    float gz_[2][3];
    gz_[0][0] = __ldg(xb + pixA);
    gz_[0][1] = __ldg(xb + 1048576 + pixA);
    gz_[0][2] = __ldg(xb + 2097152 + pixA);
    gz_[1][0] = __ldg(xb + pixB);
    gz_[1][1] = __ldg(xb + 1048576 + pixB);
    gz_[1][2] = __ldg(xb + 2097152 + pixB);

    __syncthreads();

    // ---- Pixel loop: 16 warps, lane = x, 2 rows per thread ----
    float ixf = fminf((float)w * r, 255.0f);
    float x0f = floorf(ixf);
    float wx  = ixf - x0f;
    int   x0  = (int)x0f;
    int   dx0 = x0 - xbase;
    int   dx1 = min(x0 + 1, 255) - xbase;

    #pragma unroll
    for (int k = 0; k < 2; k++) {
        const int h   = (k == 0) ? h_a : h_b;
        const int pix = (k == 0) ? pixA : pixB;

        float iyf = fminf((float)h * r, 255.0f);
        float y0f = floorf(iyf);
        float wy  = iyf - y0f;
        int   y0  = (int)y0f;
        int   dy0 = y0 - ybase;
        int   dy1 = min(y0 + 1, 255) - ybase;

        int cb00 = (dy0 * XS + dx0) * 4;
        int cb01 = (dy0 * XS + dx1) * 4;
        int cb10 = (dy1 * XS + dx0) * 4;
        int cb11 = (dy1 * XS + dx1) * 4;

        float w11 = wy * wx;
        float w10 = wy - w11;
        float w01 = wx - w11;
        float w00 = 1.0f - wy - wx + w11;

        const __half2 hw00 = __half2half2(__float2half_rn(w00));
        const __half2 hw01 = __half2half2(__float2half_rn(w01));
        const __half2 hw10 = __half2half2(__float2half_rn(w10));
        const __half2 hw11 = __half2half2(__float2half_rn(w11));

        float acc0 = 0.f, acc1 = 0.f, acc2 = 0.f;

        #pragma unroll
        for (int i = 0; i < 3; i++) {
            float gz  = gz_[k][i];
            float izf = fminf(fmaxf(fmaf(gz, 3.5f, 3.5f), 3.5f), 6.99951171875f);
            float z0f = floorf(izf);
            float wz  = izf - z0f;
            int   zi  = (int)z0f - 3;            // 0..3
            const __half2* base = sh + (i * 3) * ASTR + zi;  // channel via +ASTR imm

            #define CHAN(COFF, ACC)                                           \
            {                                                                 \
                const __half2* p = base + (COFF) * ASTR;                      \
                __half2 t = __hfma2(hw01, p[cb01], __hmul2(hw00, p[cb00]));   \
                __half2 u = __hfma2(hw11, p[cb11], __hmul2(hw10, p[cb10]));   \
                t = __hadd2(t, u);                                            \
                float2 f = __half22float2(t);                                 \
                ACC += fmaf(wz, f.y - f.x, f.x);                              \
            }
            CHAN(0, acc0)
            CHAN(1, acc1)
            CHAN(2, acc2)
            #undef CHAN
        }

        ob[pix]           = fast_tanh(acc0);
        ob[1048576 + pix] = fast_tanh(acc1);
        ob[2097152 + pix] = fast_tanh(acc2);
    }
}

extern "C" void kernel_launch(void* const* d_in, const int* in_sizes, int n_in,
                              void* d_out, int out_size)
{
    const float* x     = (const float*)d_in[0];   // [4,3,1024,1024] fp32
    const float* param = (const float*)d_in[1];   // [4,72,256,256]  fp32
    float*       out   = (float*)d_out;           // [4,3,1024,1024] fp32

    dim3 grid(1024 / TW, 1024 / TH, 4);
    curve_apply_kernel<<<grid, NTHREADS>>>(x, param, out);
}